// round 3
// baseline (speedup 1.0000x reference)
#include <cuda_runtime.h>
#include <cstdint>

// WholeMask: paste B*K 28x28 masks into 512x512 canvases (nearest-neighbor
// over rounded+clipped bbox), zero elsewhere and for k >= counts[b].
//
// R3 (= R2 resubmit; container infra failure last round): shared-memory
// "expanded canvas" — 29 rows x 512 cols (28 expanded mask rows + one zero
// row), x-predication and sx-gather baked in during setup. Per-y LUT of row
// offsets bakes in y-predication + count validity. Inner loop is pure
// LDS -> LDS.128 -> STG.128 (write-back; output is ~L2-sized).

#define MH 28
#define MW 28
#define IMG 512
#define ROW_F 512
#define CANVAS_ROWS 29            // 28 mask rows + zero row
#define SMEM_BYTES ((CANVAS_ROWS * ROW_F + IMG) * 4)   // 61440

__global__ __launch_bounds__(512, 2)
void wholemask_kernel(const float* __restrict__ bboxess,
                      const int*   __restrict__ counts,
                      const float* __restrict__ maskss,
                      float*       __restrict__ out,
                      int Kk)
{
    extern __shared__ float sm[];
    float* canvas = sm;                                   // [29][512]
    int*   soff   = (int*)(sm + CANVAS_ROWS * ROW_F);     // [512] float-offsets

    const int slice = blockIdx.x;               // b*K + k
    const int b = slice / Kk;
    const int k = slice - b * Kk;
    const int tid = threadIdx.y * blockDim.x + threadIdx.x;   // 0..511

    const bool valid = (k < counts[b]);

    // Rounded (half-even, matches jnp.round) + clipped box.
    const float4 bb = reinterpret_cast<const float4*>(bboxess)[slice];
    int y1 = __float2int_rn(bb.x);
    int x1 = __float2int_rn(bb.y);
    int y2 = __float2int_rn(bb.z);
    int x2 = __float2int_rn(bb.w);
    y1 = min(max(y1, 0), IMG - 1);
    x1 = min(max(x1, 0), IMG - 1);
    y2 = min(max(y2, y1 + 1), IMG);
    x2 = min(max(x2, x1 + 1), IMG);
    const int h = y2 - y1;
    const int w = x2 - x1;

    // ---- Setup: one column (and one y entry) per thread ----
    {
        const int x = tid;                               // 0..511
        const bool inx = valid && (x >= x1) && (x < x2);
        int sx = (x - x1) * MW / w;                      // x>=x1 inside, trunc==floor
        sx = min(max(sx, 0), MW - 1);
        const float* gm = maskss + (size_t)slice * (MH * MW);
        #pragma unroll
        for (int r = 0; r < MH; ++r)
            canvas[r * ROW_F + x] = inx ? gm[r * MW + sx] : 0.0f;
        canvas[MH * ROW_F + x] = 0.0f;                   // zero row

        // Row LUT for y = tid: offset into canvas (in floats).
        const bool iny = valid && (x >= y1) && (x < y2);
        int sy = (x - y1) * MH / h;
        sy = min(max(sy, 0), MH - 1);
        soff[x] = (iny ? sy : MH) * ROW_F;
    }
    __syncthreads();

    // ---- Main: copy canvas rows to output (256 rows per block) ----
    const int y0 = blockIdx.y * (IMG / 2);
    float* obase = out + (size_t)slice * (IMG * IMG) + (size_t)y0 * IMG;
    const int xq = threadIdx.x * 4;                      // float4 column start

    #pragma unroll 8
    for (int yy = 0; yy < IMG / 2; yy += 4) {
        const int yl = yy + threadIdx.y;                 // local row 0..255
        const float4 v = *reinterpret_cast<const float4*>(canvas + soff[y0 + yl] + xq);
        *reinterpret_cast<float4*>(obase + (size_t)yl * IMG + xq) = v;
    }
}

extern "C" void kernel_launch(void* const* d_in, const int* in_sizes, int n_in,
                              void* d_out, int out_size)
{
    const float* bboxess = (const float*)d_in[0];   // (B,K,4) f32
    const int*   counts  = (const int*)  d_in[1];   // (B,1)   i32
    const float* maskss  = (const float*)d_in[2];   // (B,K,1,28,28) f32

    const int BK = in_sizes[0] / 4;                 // B*K
    const int Bv = in_sizes[1];                     // B
    const int Kk = BK / Bv;                         // K

    cudaFuncSetAttribute(wholemask_kernel,
                         cudaFuncAttributeMaxDynamicSharedMemorySize, SMEM_BYTES);

    dim3 block(128, 4);            // 128 float4 lanes x 4 rows
    dim3 grid(BK, 2);              // 128 slices x 2 row-halves = 256 CTAs (1 wave)
    wholemask_kernel<<<grid, block, SMEM_BYTES>>>(bboxess, counts, maskss,
                                                  (float*)d_out, Kk);
}